// round 2
// baseline (speedup 1.0000x reference)
#include <cuda_runtime.h>
#include <cuda_bf16.h>
#include <math.h>

// Problem constants (MoEGate_52673478918592)
#define NE 256          // experts
#define KH 7168         // hidden dim
#define MAX_T 16384     // 4 * 4096 tokens
#define N_GROUP 8
#define EXP_PER_GROUP 32
#define TOPK_GROUP 4
#define TOP_K 8
#define ROUTED_SCALE 2.5f

// Scratch: logits [T, 256]  (16 MB device global; allocation-free rule)
__device__ float g_logits[MAX_T * NE];

// ----------------------------------------------------------------------------
// GEMM: C[M, 256] = A[M, 7168] * B[7168, 256]   (fp32 FFMA, SMEM tiled)
// Tile: BM=128, BN=64, BK=16; 256 threads; 8x4 per-thread microtile.
// ----------------------------------------------------------------------------
#define BM 128
#define BN 64
#define BK 16
#define TM 8
#define TN 4

__global__ __launch_bounds__(256, 2)
void gate_gemm_kernel(const float* __restrict__ A,
                      const float* __restrict__ B,
                      float* __restrict__ C,
                      int M)
{
    __shared__ float As[BK][BM];     // k-major A tile (transposed on store)
    __shared__ float Bs[BK][BN];

    const int bx = blockIdx.x;       // N tile index (0..3)
    const int by = blockIdx.y;       // M tile index
    const int tid = threadIdx.x;

    // compute-phase thread coords
    const int tx = tid & 15;         // 16 cols of TN=4  -> covers BN=64
    const int ty = tid >> 4;         // 16 rows of TM=8  -> covers BM=128

    // A-load coords: 128 rows x 4 float4-chunks along K; 2 rows per thread
    const int a_row  = tid >> 2;     // 0..63  (+64 for second)
    const int a_col4 = tid & 3;      // float4 chunk within BK

    // B-load coords: 16 k-rows x 16 float4-chunks; 1 per thread
    const int b_row  = tid >> 4;     // 0..15 (k)
    const int b_col4 = tid & 15;     // 0..15 (n/4)

    const float* Aptr = A + (size_t)(by * BM) * KH;
    const float* Bptr = B + bx * BN;

    float acc[TM][TN];
    #pragma unroll
    for (int i = 0; i < TM; ++i)
        #pragma unroll
        for (int j = 0; j < TN; ++j)
            acc[i][j] = 0.0f;

    for (int k0 = 0; k0 < KH; k0 += BK) {
        // --- load A tile (transposed into As[k][m]) ---
        #pragma unroll
        for (int r = 0; r < 2; ++r) {
            const int row = a_row + r * 64;
            float4 v = *(const float4*)(Aptr + (size_t)row * KH + k0 + a_col4 * 4);
            As[a_col4 * 4 + 0][row] = v.x;
            As[a_col4 * 4 + 1][row] = v.y;
            As[a_col4 * 4 + 2][row] = v.z;
            As[a_col4 * 4 + 3][row] = v.w;
        }
        // --- load B tile ---
        {
            float4 v = *(const float4*)(Bptr + (size_t)(k0 + b_row) * NE + b_col4 * 4);
            *(float4*)&Bs[b_row][b_col4 * 4] = v;
        }
        __syncthreads();

        #pragma unroll
        for (int kk = 0; kk < BK; ++kk) {
            float a0[TM], b0[TN];
            // vectorized smem reads
            const float4 av0 = *(const float4*)&As[kk][ty * TM];
            const float4 av1 = *(const float4*)&As[kk][ty * TM + 4];
            a0[0] = av0.x; a0[1] = av0.y; a0[2] = av0.z; a0[3] = av0.w;
            a0[4] = av1.x; a0[5] = av1.y; a0[6] = av1.z; a0[7] = av1.w;
            const float4 bv = *(const float4*)&Bs[kk][tx * TN];
            b0[0] = bv.x; b0[1] = bv.y; b0[2] = bv.z; b0[3] = bv.w;

            #pragma unroll
            for (int i = 0; i < TM; ++i)
                #pragma unroll
                for (int j = 0; j < TN; ++j)
                    acc[i][j] = fmaf(a0[i], b0[j], acc[i][j]);
        }
        __syncthreads();
    }

    // --- write C ---
    #pragma unroll
    for (int i = 0; i < TM; ++i) {
        const int row = by * BM + ty * TM + i;
        float4 v;
        v.x = acc[i][0]; v.y = acc[i][1]; v.z = acc[i][2]; v.w = acc[i][3];
        *(float4*)&C[(size_t)row * NE + bx * BN + tx * TN] = v;
    }
}

// ----------------------------------------------------------------------------
// Routing: one warp per token.
// Lane l owns experts [l*8, l*8+8). Group g = lanes 4g..4g+3.
// ----------------------------------------------------------------------------
__global__ __launch_bounds__(256)
void route_kernel(const float* __restrict__ logits,
                  const float* __restrict__ bias,
                  float* __restrict__ out_idx,   // [T*8] as float
                  float* __restrict__ out_w,     // [T*8]
                  int T)
{
    const int gwarp = (blockIdx.x * blockDim.x + threadIdx.x) >> 5;
    const int lane = threadIdx.x & 31;
    if (gwarp >= T) return;

    const float* lp = logits + (size_t)gwarp * NE;

    // scores_for_choice = sigmoid(logit) + bias
    float s[8];
    #pragma unroll
    for (int j = 0; j < 8; ++j) {
        const int e = lane * 8 + j;
        const float x = lp[e];
        const float sg = 1.0f / (1.0f + expf(-x));
        s[j] = sg + bias[e];
    }

    // --- per-lane top-2 of its 8 scores ---
    float m1 = -1e30f, m2 = -1e30f;
    #pragma unroll
    for (int j = 0; j < 8; ++j) {
        const float v = s[j];
        if (v > m1) { m2 = m1; m1 = v; }
        else if (v > m2) { m2 = v; }
    }
    // --- merge across the 4 lanes of each group ---
    #pragma unroll
    for (int off = 1; off < 4; off <<= 1) {
        const float o1 = __shfl_xor_sync(0xffffffffu, m1, off);
        const float o2 = __shfl_xor_sync(0xffffffffu, m2, off);
        const float n1 = fmaxf(m1, o1);
        const float n2 = fmaxf(fminf(m1, o1), fmaxf(m2, o2));
        m1 = n1; m2 = n2;
    }
    const float gscore = m1 + m2;   // identical on all 4 lanes of the group

    // --- gather all 8 group scores, select top-4 groups (ties -> lowest g) ---
    float gs[N_GROUP];
    #pragma unroll
    for (int g = 0; g < N_GROUP; ++g)
        gs[g] = __shfl_sync(0xffffffffu, gscore, g * 4);

    unsigned gmask = 0;
    #pragma unroll
    for (int t = 0; t < TOPK_GROUP; ++t) {
        int best = 0; float bv = -1e30f;
        #pragma unroll
        for (int g = 0; g < N_GROUP; ++g) {
            if (!((gmask >> g) & 1u) && gs[g] > bv) { bv = gs[g]; best = g; }
        }
        gmask |= 1u << best;
    }

    const bool sel = (gmask >> (lane >> 2)) & 1u;

    // masked value exactly as reference: sel ? score : 0.0
    float mv[8];
    #pragma unroll
    for (int j = 0; j < 8; ++j) mv[j] = sel ? s[j] : 0.0f;

    // --- iterative warp argmax, 8 picks, ties -> lowest expert index ---
    bool used[8];
    #pragma unroll
    for (int j = 0; j < 8; ++j) used[j] = false;

    float my_v = 0.0f;
    int my_i = 0;
    float vsum = 0.0f;

    #pragma unroll
    for (int t = 0; t < TOP_K; ++t) {
        float bv = -1e30f; int bi = NE;
        #pragma unroll
        for (int j = 0; j < 8; ++j) {
            if (!used[j]) {
                const float v = mv[j];
                const int e = lane * 8 + j;
                if (v > bv || (v == bv && e < bi)) { bv = v; bi = e; }
            }
        }
        #pragma unroll
        for (int off = 16; off > 0; off >>= 1) {
            const float ov = __shfl_xor_sync(0xffffffffu, bv, off);
            const int   oi = __shfl_xor_sync(0xffffffffu, bi, off);
            if (ov > bv || (ov == bv && oi < bi)) { bv = ov; bi = oi; }
        }
        if ((bi >> 3) == lane) used[bi & 7] = true;
        if (lane == t) { my_v = bv; my_i = bi; }
        vsum += bv;
    }

    const float scale = ROUTED_SCALE / (vsum + 1e-20f);
    if (lane < TOP_K) {
        out_idx[(size_t)gwarp * TOP_K + lane] = (float)my_i;
        out_w  [(size_t)gwarp * TOP_K + lane] = my_v * scale;
    }
}

// ----------------------------------------------------------------------------
// Launch
// ----------------------------------------------------------------------------
extern "C" void kernel_launch(void* const* d_in, const int* in_sizes, int n_in,
                              void* d_out, int out_size)
{
    const float* hs   = (const float*)d_in[0];   // [4, 4096, 7168]
    const float* wk   = (const float*)d_in[1];   // [7168, 256]
    const float* bias = (const float*)d_in[2];   // [256]

    const int T = in_sizes[0] / KH;              // 16384

    float* logits;
    cudaGetSymbolAddress((void**)&logits, g_logits);

    // GEMM
    dim3 grid(NE / BN, T / BM);
    gate_gemm_kernel<<<grid, 256>>>(hs, wk, logits, T);

    // Routing: 8 warps (tokens) per block
    float* out_f = (float*)d_out;
    float* out_idx = out_f;                       // [T*8] indices as float
    float* out_w   = out_f + (size_t)T * TOP_K;   // [T*8] weights
    const int warps_per_block = 8;
    const int nblocks = (T + warps_per_block - 1) / warps_per_block;
    route_kernel<<<nblocks, warps_per_block * 32>>>(logits, bias, out_idx, out_w, T);
}